// round 12
// baseline (speedup 1.0000x reference)
#include <cuda_runtime.h>
#include <cuda_bf16.h>
#include <cstdint>

#define BB 8
#define SS 2048
#define DD 256
#define UU 128
#define MM (BB*SS)

// ---------------- device scratch (bf16 staging) ----------------
__device__ __nv_bfloat16 g_Qb[MM*UU];
__device__ __nv_bfloat16 g_Kb[MM*UU];
__device__ __nv_bfloat16 g_Vb[MM*UU];
__device__ __nv_bfloat16 g_Ob[MM*UU];
__device__ __nv_bfloat16 g_Wq[DD*UU], g_Wk[DD*UU], g_Wv[DD*UU];
__device__ __nv_bfloat16 g_Wo[UU*DD];

// ---------------- helpers ----------------
__device__ __forceinline__ uint32_t smem_u32(const void* p){
    uint32_t a;
    asm("{ .reg .u64 t; cvta.to.shared.u64 t, %1; cvt.u32.u64 %0, t; }":"=r"(a):"l"(p));
    return a;
}
__device__ __forceinline__ float ex2f(float x){
    float r; asm("ex2.approx.ftz.f32 %0, %1;":"=f"(r):"f"(x)); return r;
}
__device__ __forceinline__ void mma_bf16(float* c, const uint32_t* a, const uint32_t* b){
    asm volatile("mma.sync.aligned.m16n8k16.row.col.f32.bf16.bf16.f32 "
        "{%0,%1,%2,%3}, {%4,%5,%6,%7}, {%8,%9}, {%0,%1,%2,%3};"
        : "+f"(c[0]),"+f"(c[1]),"+f"(c[2]),"+f"(c[3])
        : "r"(a[0]),"r"(a[1]),"r"(a[2]),"r"(a[3]), "r"(b[0]),"r"(b[1]));
}
__device__ __forceinline__ void ldsm_x4(uint32_t* r, uint32_t addr){
    asm volatile("ldmatrix.sync.aligned.m8n8.x4.shared.b16 {%0,%1,%2,%3}, [%4];"
        : "=r"(r[0]),"=r"(r[1]),"=r"(r[2]),"=r"(r[3]) : "r"(addr));
}
__device__ __forceinline__ void ldsm_x4_t(uint32_t* r, uint32_t addr){
    asm volatile("ldmatrix.sync.aligned.m8n8.x4.trans.shared.b16 {%0,%1,%2,%3}, [%4];"
        : "=r"(r[0]),"=r"(r[1]),"=r"(r[2]),"=r"(r[3]) : "r"(addr));
}
#define CP16(dst, src) asm volatile("cp.async.cg.shared.global [%0], [%1], 16;" :: "r"(dst), "l"(src) : "memory")
#define CP_COMMIT()    asm volatile("cp.async.commit_group;" ::: "memory")
#define CP_WAIT0()     asm volatile("cp.async.wait_group 0;" ::: "memory")
#define CP_WAIT1()     asm volatile("cp.async.wait_group 1;" ::: "memory")

// ===========================================================================
// Weights fp32 -> bf16 convert
// ===========================================================================
#define NW4 (DD*UU/4)
__global__ void conv_w(const float* __restrict__ Wq, const float* __restrict__ Wk,
                       const float* __restrict__ Wv, const float* __restrict__ Wo,
                       __nv_bfloat16* __restrict__ wq, __nv_bfloat16* __restrict__ wk,
                       __nv_bfloat16* __restrict__ wv, __nv_bfloat16* __restrict__ wo)
{
    int i = blockIdx.x * blockDim.x + threadIdx.x;
    const float* src; __nv_bfloat16* dst; int j;
    if (i < NW4)              { src = Wq; dst = wq; j = i; }
    else if (i < 2*NW4)       { src = Wk; dst = wk; j = i - NW4; }
    else if (i < 3*NW4)       { src = Wv; dst = wv; j = i - 2*NW4; }
    else if (i < 4*NW4)       { src = Wo; dst = wo; j = i - 3*NW4; }
    else return;
    float4 v = ((const float4*)src)[j];
    __nv_bfloat162 a = __floats2bfloat162_rn(v.x, v.y);
    __nv_bfloat162 b = __floats2bfloat162_rn(v.z, v.w);
    uint2 o; o.x = *(uint32_t*)&a; o.y = *(uint32_t*)&b;
    ((uint2*)dst)[j] = o;
}

// ===========================================================================
// QKV projection (round-11, passing): X fp32 direct + in-register convert
// ===========================================================================
#define QKV_SMEM 49152
__global__ void __launch_bounds__(256, 3)
qkv_mma(const float* __restrict__ X,
        const __nv_bfloat16* __restrict__ Wqb, const __nv_bfloat16* __restrict__ Wkb,
        const __nv_bfloat16* __restrict__ Wvb,
        __nv_bfloat16* __restrict__ Qb, __nv_bfloat16* __restrict__ Kb,
        __nv_bfloat16* __restrict__ Vb)
{
    extern __shared__ __align__(128) char sm[];
    const uint32_t sb = smem_u32(sm);
    const int t = threadIdx.x, w = t >> 5, lane = t & 31, l7 = lane & 7;
    const int qg = w & 3, cg = w >> 2;
    const int z = blockIdx.y;
    const __nv_bfloat16* Wb = (z == 0) ? Wqb : (z == 1) ? Wkb : Wvb;
    __nv_bfloat16* Ob = (z == 0) ? Qb : (z == 1) ? Kb : Vb;
    const int rowBase = blockIdx.x * 64;
    const float* Xg = X + (size_t)rowBase * DD;
    const char* Wg = (const char*)Wb;

    float4 xr[4];
    const int xrow = t >> 4, xc4 = t & 15;
    auto ldg_x = [&](int kc){
#pragma unroll
        for (int q = 0; q < 4; q++)
            xr[q] = *(const float4*)(Xg + (size_t)(xrow + q*16)*DD + kc*64 + xc4*4);
    };
    auto sts_x = [&](int buf){
        char* xd = sm + buf*8192;
#pragma unroll
        for (int q = 0; q < 4; q++){
            int row = xrow + q*16;
            __nv_bfloat162 a = __floats2bfloat162_rn(xr[q].x, xr[q].y);
            __nv_bfloat162 b = __floats2bfloat162_rn(xr[q].z, xr[q].w);
            uint32_t off = (uint32_t)row*128u
                         + (uint32_t)((((xc4 >> 1)) ^ (row & 7)) << 4)
                         + (uint32_t)((xc4 & 1) * 8);
            uint2 v; v.x = *(uint32_t*)&a; v.y = *(uint32_t*)&b;
            *(uint2*)(xd + off) = v;
        }
    };
    auto load_w = [&](int kc, int buf){
        uint32_t wd = sb + 16384 + (uint32_t)buf * 16384;
#pragma unroll
        for (int q = 0; q < 4; q++){
            int idx = t + q*256, row = idx >> 4, ch = idx & 15;
            CP16(wd + row*256 + (uint32_t)((ch ^ (row & 7)) << 4),
                 Wg + (size_t)(kc*64 + row)*256 + ch*16);
        }
        CP_COMMIT();
    };

    float acc[8][4];
#pragma unroll
    for (int i = 0; i < 8; i++)
#pragma unroll
        for (int j = 0; j < 4; j++) acc[i][j] = 0.f;

    ldg_x(0);
    load_w(0, 0);
    load_w(1, 1);
    sts_x(0);
    ldg_x(1);

    for (int kc = 0; kc < 4; kc++){
        if (kc < 3) CP_WAIT1(); else CP_WAIT0();
        __syncthreads();
        const uint32_t xb = sb + (uint32_t)(kc & 1)*8192;
        const uint32_t wb = sb + 16384 + (uint32_t)(kc & 1)*16384;
#pragma unroll
        for (int t4 = 0; t4 < 4; t4++){
            uint32_t a[4];
            int arow = 16*qg + (lane & 15);
            int ach  = 2*t4 + (lane >> 4);
            ldsm_x4(a, xb + arow*128 + (uint32_t)((ach ^ (arow & 7)) << 4));
            int krow = 16*t4 + l7 + ((lane >> 3) & 1)*8;
#pragma unroll
            for (int u2 = 0; u2 < 4; u2++){
                uint32_t bv[4];
                int ch = 2*(4*cg + u2) + (lane >> 4);
                ldsm_x4_t(bv, wb + krow*256 + (uint32_t)((ch ^ l7) << 4));
                mma_bf16(acc[2*u2],     a, bv);
                mma_bf16(acc[2*u2 + 1], a, bv + 2);
            }
        }
        __syncthreads();
        if (kc < 3) sts_x((kc + 1) & 1);
        if (kc < 2){ ldg_x(kc + 2); load_w(kc + 2, kc & 1); }
    }

    __syncthreads();
    uint32_t* st = (uint32_t*)sm;
    {
        int r = 16*qg + (lane >> 2);
        int c2base = 32*cg + (lane & 3);
#pragma unroll
        for (int nt = 0; nt < 8; nt++){
            __nv_bfloat162 h0 = __floats2bfloat162_rn(acc[nt][0], acc[nt][1]);
            __nv_bfloat162 h1 = __floats2bfloat162_rn(acc[nt][2], acc[nt][3]);
            st[r*68 + c2base + 4*nt]       = *(uint32_t*)&h0;
            st[(r + 8)*68 + c2base + 4*nt] = *(uint32_t*)&h1;
        }
    }
    __syncthreads();
#pragma unroll
    for (int p = 0; p < 4; p++){
        int row = (t >> 4) + p*16;
        int u4  = t & 15;
        uint4 v = *(uint4*)(st + row*68 + u4*4);
        *(uint4*)(Ob + (size_t)(rowBase + row)*UU + u4*8) = v;
    }
}

// ===========================================================================
// Output projection (round-11, passing)
// ===========================================================================
#define PROJ_SMEM 49152
__global__ void __launch_bounds__(256, 3)
proj_mma(const __nv_bfloat16* __restrict__ Ab, const __nv_bfloat16* __restrict__ Wob,
         float* __restrict__ C, const float* __restrict__ bias,
         const float* __restrict__ res)
{
    extern __shared__ __align__(128) char sm[];
    const uint32_t sb = smem_u32(sm);
    const int t = threadIdx.x, w = t >> 5, lane = t & 31, l7 = lane & 7;
    const int qg = w & 3, cg = w >> 2;
    const int rowBase = blockIdx.y * 64, colBase = blockIdx.x * 128;

    const char* Ag = (const char*)(Ab + (size_t)rowBase * UU);
    const char* Wg = (const char*)Wob + (size_t)colBase * 2;
#pragma unroll
    for (int q = 0; q < 4; q++){
        int idx = t + q*256, row = idx >> 4, ch = idx & 15;
        CP16(sb + row*256 + (uint32_t)((ch ^ (row & 7)) << 4),
             Ag + (size_t)row*256 + ch*16);
    }
#pragma unroll
    for (int q = 0; q < 8; q++){
        int idx = t + q*256, row = idx >> 4, ch = idx & 15;
        CP16(sb + 16384 + row*256 + (uint32_t)((ch ^ (row & 7)) << 4),
             Wg + (size_t)row*512 + ch*16);
    }
    CP_COMMIT();
    CP_WAIT0();
    __syncthreads();

    float acc[8][4];
#pragma unroll
    for (int i = 0; i < 8; i++)
#pragma unroll
        for (int j = 0; j < 4; j++) acc[i][j] = 0.f;

#pragma unroll
    for (int t4 = 0; t4 < 8; t4++){
        uint32_t a[4];
        int arow = 16*qg + (lane & 15);
        int ach  = 2*t4 + (lane >> 4);
        ldsm_x4(a, sb + arow*256 + (uint32_t)((ach ^ (arow & 7)) << 4));
        int krow = 16*t4 + l7 + ((lane >> 3) & 1)*8;
#pragma unroll
        for (int u2 = 0; u2 < 4; u2++){
            uint32_t bv[4];
            int ch = 2*(4*cg + u2) + (lane >> 4);
            ldsm_x4_t(bv, sb + 16384 + krow*256 + (uint32_t)((ch ^ l7) << 4));
            mma_bf16(acc[2*u2],     a, bv);
            mma_bf16(acc[2*u2 + 1], a, bv + 2);
        }
    }

    __syncthreads();
    float* st = (float*)sm;
    {
        int r = 16*qg + (lane >> 2);
        int cb = 64*cg + 2*(lane & 3);
#pragma unroll
        for (int nt = 0; nt < 8; nt++){
            int c = cb + 8*nt;
            st[r*132 + c]           = acc[nt][0];
            st[r*132 + c + 1]       = acc[nt][1];
            st[(r + 8)*132 + c]     = acc[nt][2];
            st[(r + 8)*132 + c + 1] = acc[nt][3];
        }
    }
    __syncthreads();
#pragma unroll
    for (int p = 0; p < 8; p++){
        int row = (t >> 5) + p*8;
        int c4  = t & 31;
        float4 v  = *(float4*)(st + row*132 + c4*4);
        float4 bi = *(const float4*)(bias + colBase + c4*4);
        float4 rs = *(const float4*)(res + (size_t)(rowBase + row)*DD + colBase + c4*4);
        v.x += bi.x + rs.x; v.y += bi.y + rs.y;
        v.z += bi.z + rs.z; v.w += bi.w + rs.w;
        *(float4*)(C + (size_t)(rowBase + row)*DD + colBase + c4*4) = v;
    }
}

// ===========================================================================
// Flash attention: 64 q-row CTAs (grid 256 for wave packing on 148 SMs).
// 8 warps = 2 q-groups (32 rows) x 4 key-groups (32 keys of each 128-key tile).
// End: 4-way O/lsum partial combine through smem, coalesced bf16 write.
// smem: KV 2 stages x 64KB = 128KB (mainloop); then P[4][64][132] f32 + L[4][64].
// ===========================================================================
#define ATT_PSTRIDE 132
#define ATT_LOFF    (4*64*ATT_PSTRIDE)              // float offset of L
#define ATT_SMEM    (ATT_LOFF*4 + 4*64*4 + 256)     // ~136.5KB

__device__ __forceinline__ void load_kv(uint32_t dst, const char* Kg, const char* Vg,
                                        int tile, int t){
    const char* ks = Kg + (size_t)tile * 128 * 256;
    const char* vs = Vg + (size_t)tile * 128 * 256;
#pragma unroll
    for (int q = 0; q < 8; q++){
        int idx = t + q*256;
        int row = idx >> 4, ch = idx & 15;
        uint32_t d = dst + row*256 + (uint32_t)((ch ^ (row & 7)) << 4);
        CP16(d,         ks + (size_t)row*256 + ch*16);
        CP16(d + 32768, vs + (size_t)row*256 + ch*16);
    }
    CP_COMMIT();
}

__global__ void __launch_bounds__(256, 1)
attn_mma(const __nv_bfloat16* __restrict__ Q, const __nv_bfloat16* __restrict__ K,
         const __nv_bfloat16* __restrict__ V, __nv_bfloat16* __restrict__ O)
{
    extern __shared__ __align__(128) char sm[];
    const uint32_t sb = smem_u32(sm);
    const int t = threadIdx.x, w = t >> 5, lane = t & 31, l7 = lane & 7;
    const int qg = w & 1, kg = w >> 1;          // 2 q-groups x 4 key-groups
    const int b = blockIdx.y, qb = blockIdx.x;  // 64-row q tile

    // ---- stage Q (64x128 bf16 = 16KB) then load A-fragments ----
    const char* Qg = (const char*)(Q + (size_t)(b*SS + qb*64)*UU);
#pragma unroll
    for (int q = 0; q < 4; q++){
        int idx = t + q*256;
        int row = idx >> 4, ch = idx & 15;
        CP16(sb + row*256 + (uint32_t)((ch ^ (row & 7)) << 4),
             Qg + (size_t)row*256 + ch*16);
    }
    CP_COMMIT();
    CP_WAIT0();
    __syncthreads();

    uint32_t qa[2][8][4];
#pragma unroll
    for (int rb = 0; rb < 2; rb++){
        int row = 32*qg + 16*rb + (lane & 15);
        int rx  = row & 7;
        int cb  = (lane >> 4) & 1;
#pragma unroll
        for (int kt = 0; kt < 8; kt++){
            int chunk = 2*kt + cb;
            ldsm_x4(qa[rb][kt], sb + row*256 + (uint32_t)((chunk ^ rx) << 4));
        }
    }
    __syncthreads();

    float oa[2][16][4];
#pragma unroll
    for (int rb = 0; rb < 2; rb++)
#pragma unroll
        for (int i = 0; i < 16; i++)
#pragma unroll
            for (int j = 0; j < 4; j++) oa[rb][i][j] = 0.f;
    float ls[2][2] = {{0.f,0.f},{0.f,0.f}};

    const char* Kg = (const char*)(K + (size_t)(b*SS)*UU);
    const char* Vg = (const char*)(V + (size_t)(b*SS)*UU);

    load_kv(sb,         Kg, Vg, 0, t);
    load_kv(sb + 65536, Kg, Vg, 1, t);

    const float C = 0.12751751699104088f;   // log2(e) / sqrt(128)

    for (int i = 0; i < 16; i++){
        if (i < 15) CP_WAIT1(); else CP_WAIT0();
        __syncthreads();
        const uint32_t kbuf = sb + (uint32_t)(i & 1)*65536;
        const uint32_t vbuf = kbuf + 32768;

#pragma unroll
        for (int tt2 = 0; tt2 < 2; tt2++){          // 16-key groups in my 32-key quarter
            const int kb = 32*kg + 16*tt2;
            float sa[2][2][4];
#pragma unroll
            for (int rb = 0; rb < 2; rb++)
#pragma unroll
                for (int jj = 0; jj < 2; jj++)
#pragma unroll
                    for (int j = 0; j < 4; j++) sa[rb][jj][j] = 0.f;
#pragma unroll
            for (int jj = 0; jj < 2; jj++){
                int row = kb + 8*jj + l7;
#pragma unroll
                for (int c = 0; c < 4; c++){
                    uint32_t bv[4];
                    int chunk = 4*c + (lane >> 3);
                    ldsm_x4(bv, kbuf + row*256 + (uint32_t)((chunk ^ l7) << 4));
                    mma_bf16(sa[0][jj], qa[0][2*c],   bv);
                    mma_bf16(sa[0][jj], qa[0][2*c+1], bv + 2);
                    mma_bf16(sa[1][jj], qa[1][2*c],   bv);
                    mma_bf16(sa[1][jj], qa[1][2*c+1], bv + 2);
                }
            }
            uint32_t pa[2][4];
#pragma unroll
            for (int rb = 0; rb < 2; rb++){
                float e00 = ex2f(sa[rb][0][0]*C), e01 = ex2f(sa[rb][0][1]*C);
                float e02 = ex2f(sa[rb][0][2]*C), e03 = ex2f(sa[rb][0][3]*C);
                float e10 = ex2f(sa[rb][1][0]*C), e11 = ex2f(sa[rb][1][1]*C);
                float e12 = ex2f(sa[rb][1][2]*C), e13 = ex2f(sa[rb][1][3]*C);
                ls[rb][0] += e00 + e01 + e10 + e11;
                ls[rb][1] += e02 + e03 + e12 + e13;
                __nv_bfloat162 h;
                h = __floats2bfloat162_rn(e00, e01); pa[rb][0] = *(uint32_t*)&h;
                h = __floats2bfloat162_rn(e02, e03); pa[rb][1] = *(uint32_t*)&h;
                h = __floats2bfloat162_rn(e10, e11); pa[rb][2] = *(uint32_t*)&h;
                h = __floats2bfloat162_rn(e12, e13); pa[rb][3] = *(uint32_t*)&h;
            }
            int vrow = kb + l7 + ((lane >> 3) & 1) * 8;
#pragma unroll
            for (int u2 = 0; u2 < 8; u2++){
                uint32_t bv[4];
                int chunk = 2*u2 + (lane >> 4);
                ldsm_x4_t(bv, vbuf + vrow*256 + (uint32_t)((chunk ^ l7) << 4));
                mma_bf16(oa[0][2*u2],     pa[0], bv);
                mma_bf16(oa[0][2*u2 + 1], pa[0], bv + 2);
                mma_bf16(oa[1][2*u2],     pa[1], bv);
                mma_bf16(oa[1][2*u2 + 1], pa[1], bv + 2);
            }
        }
        if (i < 14){
            __syncthreads();
            load_kv(sb + (uint32_t)(i & 1)*65536, Kg, Vg, i + 2, t);
        }
    }

    // ---- quad-reduce partial row sums ----
#pragma unroll
    for (int rb = 0; rb < 2; rb++)
#pragma unroll
        for (int j = 0; j < 2; j++){
            ls[rb][j] += __shfl_xor_sync(0xffffffffu, ls[rb][j], 1);
            ls[rb][j] += __shfl_xor_sync(0xffffffffu, ls[rb][j], 2);
        }

    // ---- 4-way key-group combine through smem ----
    float* P = (float*)sm;                        // [4][64][ATT_PSTRIDE]
    float* L = (float*)sm + ATT_LOFF;             // [4][64]
    __syncthreads();
#pragma unroll
    for (int rb = 0; rb < 2; rb++){
        int r0 = 32*qg + 16*rb + (lane >> 2);
        int c0 = 2*(lane & 3);
        float* Pr  = P + (kg*64 + r0)*ATT_PSTRIDE;
        float* Pr8 = P + (kg*64 + r0 + 8)*ATT_PSTRIDE;
#pragma unroll
        for (int nt = 0; nt < 16; nt++){
            Pr[nt*8 + c0]      = oa[rb][nt][0];
            Pr[nt*8 + c0 + 1]  = oa[rb][nt][1];
            Pr8[nt*8 + c0]     = oa[rb][nt][2];
            Pr8[nt*8 + c0 + 1] = oa[rb][nt][3];
        }
        if ((lane & 3) == 0){
            L[kg*64 + r0]     = ls[rb][0];
            L[kg*64 + r0 + 8] = ls[rb][1];
        }
    }
    __syncthreads();

    // ---- combine + coalesced bf16 write ----
    __nv_bfloat16* Obase = O + (size_t)(b*SS + qb*64)*UU;
#pragma unroll
    for (int p = 0; p < 4; p++){
        int row = (t >> 4) + p*16;       // 0..63
        int u4  = t & 15;                // float4 group within 128 cols
        float inv = 1.f / (L[row] + L[64 + row] + L[128 + row] + L[192 + row]);
        float s[8];
#pragma unroll
        for (int e = 0; e < 8; e++) s[e] = 0.f;
#pragma unroll
        for (int k4 = 0; k4 < 4; k4++){
            const float* Pr = P + (k4*64 + row)*ATT_PSTRIDE + u4*8;
            float4 a = *(const float4*)(Pr);
            float4 b2 = *(const float4*)(Pr + 4);
            s[0] += a.x; s[1] += a.y; s[2] += a.z; s[3] += a.w;
            s[4] += b2.x; s[5] += b2.y; s[6] += b2.z; s[7] += b2.w;
        }
        uint4 out;
        __nv_bfloat162 h;
        h = __floats2bfloat162_rn(s[0]*inv, s[1]*inv); out.x = *(uint32_t*)&h;
        h = __floats2bfloat162_rn(s[2]*inv, s[3]*inv); out.y = *(uint32_t*)&h;
        h = __floats2bfloat162_rn(s[4]*inv, s[5]*inv); out.z = *(uint32_t*)&h;
        h = __floats2bfloat162_rn(s[6]*inv, s[7]*inv); out.w = *(uint32_t*)&h;
        *(uint4*)(Obase + (size_t)row*UU + u4*8) = out;
    }
}

// ===========================================================================
extern "C" void kernel_launch(void* const* d_in, const int* in_sizes, int n_in,
                              void* d_out, int out_size)
{
    const float* X   = (const float*)d_in[0];
    const float* W_q = (const float*)d_in[1];
    const float* W_k = (const float*)d_in[2];
    const float* W_v = (const float*)d_in[3];
    const float* W_o = (const float*)d_in[4];
    const float* b_o = (const float*)d_in[5];
    float* out = (float*)d_out;

    __nv_bfloat16 *qb, *kb, *vb, *ob, *wq, *wk, *wv, *wo;
    cudaGetSymbolAddress((void**)&qb, g_Qb);
    cudaGetSymbolAddress((void**)&kb, g_Kb);
    cudaGetSymbolAddress((void**)&vb, g_Vb);
    cudaGetSymbolAddress((void**)&ob, g_Ob);
    cudaGetSymbolAddress((void**)&wq, g_Wq);
    cudaGetSymbolAddress((void**)&wk, g_Wk);
    cudaGetSymbolAddress((void**)&wv, g_Wv);
    cudaGetSymbolAddress((void**)&wo, g_Wo);

    cudaFuncSetAttribute(qkv_mma,  cudaFuncAttributeMaxDynamicSharedMemorySize, QKV_SMEM);
    cudaFuncSetAttribute(attn_mma, cudaFuncAttributeMaxDynamicSharedMemorySize, ATT_SMEM);
    cudaFuncSetAttribute(proj_mma, cudaFuncAttributeMaxDynamicSharedMemorySize, PROJ_SMEM);

    conv_w<<<(4*NW4 + 255)/256, 256>>>(W_q, W_k, W_v, W_o, wq, wk, wv, wo);
    qkv_mma<<<dim3(MM/64, 3), 256, QKV_SMEM>>>(X, wq, wk, wv, qb, kb, vb);
    attn_mma<<<dim3(SS/64, BB), 256, ATT_SMEM>>>(qb, kb, vb, ob);
    proj_mma<<<dim3(DD/128, MM/64), 256, PROJ_SMEM>>>(ob, wo, out, b_o, X);
}

// round 13
// speedup vs baseline: 1.1243x; 1.1243x over previous
#include <cuda_runtime.h>
#include <cuda_bf16.h>
#include <cstdint>

#define BB 8
#define SS 2048
#define DD 256
#define UU 128
#define MM (BB*SS)

// ---------------- device scratch (bf16 staging) ----------------
__device__ __nv_bfloat16 g_Qb[MM*UU];
__device__ __nv_bfloat16 g_Kb[MM*UU];
__device__ __nv_bfloat16 g_Vb[MM*UU];
__device__ __nv_bfloat16 g_Ob[MM*UU];
__device__ __nv_bfloat16 g_Wq[DD*UU], g_Wk[DD*UU], g_Wv[DD*UU];
__device__ __nv_bfloat16 g_Wo[UU*DD];

// ---------------- helpers ----------------
__device__ __forceinline__ uint32_t smem_u32(const void* p){
    uint32_t a;
    asm("{ .reg .u64 t; cvta.to.shared.u64 t, %1; cvt.u32.u64 %0, t; }":"=r"(a):"l"(p));
    return a;
}
__device__ __forceinline__ float ex2f(float x){
    float r; asm("ex2.approx.ftz.f32 %0, %1;":"=f"(r):"f"(x)); return r;
}
__device__ __forceinline__ void mma_bf16(float* c, const uint32_t* a, const uint32_t* b){
    asm volatile("mma.sync.aligned.m16n8k16.row.col.f32.bf16.bf16.f32 "
        "{%0,%1,%2,%3}, {%4,%5,%6,%7}, {%8,%9}, {%0,%1,%2,%3};"
        : "+f"(c[0]),"+f"(c[1]),"+f"(c[2]),"+f"(c[3])
        : "r"(a[0]),"r"(a[1]),"r"(a[2]),"r"(a[3]), "r"(b[0]),"r"(b[1]));
}
__device__ __forceinline__ void ldsm_x4(uint32_t* r, uint32_t addr){
    asm volatile("ldmatrix.sync.aligned.m8n8.x4.shared.b16 {%0,%1,%2,%3}, [%4];"
        : "=r"(r[0]),"=r"(r[1]),"=r"(r[2]),"=r"(r[3]) : "r"(addr));
}
__device__ __forceinline__ void ldsm_x4_t(uint32_t* r, uint32_t addr){
    asm volatile("ldmatrix.sync.aligned.m8n8.x4.trans.shared.b16 {%0,%1,%2,%3}, [%4];"
        : "=r"(r[0]),"=r"(r[1]),"=r"(r[2]),"=r"(r[3]) : "r"(addr));
}
#define CP16(dst, src) asm volatile("cp.async.cg.shared.global [%0], [%1], 16;" :: "r"(dst), "l"(src) : "memory")
#define CP_COMMIT()    asm volatile("cp.async.commit_group;" ::: "memory")
#define CP_WAIT0()     asm volatile("cp.async.wait_group 0;" ::: "memory")
#define CP_WAIT1()     asm volatile("cp.async.wait_group 1;" ::: "memory")

// ===========================================================================
// Weights fp32 -> bf16 convert
// ===========================================================================
#define NW4 (DD*UU/4)
__global__ void conv_w(const float* __restrict__ Wq, const float* __restrict__ Wk,
                       const float* __restrict__ Wv, const float* __restrict__ Wo,
                       __nv_bfloat16* __restrict__ wq, __nv_bfloat16* __restrict__ wk,
                       __nv_bfloat16* __restrict__ wv, __nv_bfloat16* __restrict__ wo)
{
    int i = blockIdx.x * blockDim.x + threadIdx.x;
    const float* src; __nv_bfloat16* dst; int j;
    if (i < NW4)              { src = Wq; dst = wq; j = i; }
    else if (i < 2*NW4)       { src = Wk; dst = wk; j = i - NW4; }
    else if (i < 3*NW4)       { src = Wv; dst = wv; j = i - 2*NW4; }
    else if (i < 4*NW4)       { src = Wo; dst = wo; j = i - 3*NW4; }
    else return;
    float4 v = ((const float4*)src)[j];
    __nv_bfloat162 a = __floats2bfloat162_rn(v.x, v.y);
    __nv_bfloat162 b = __floats2bfloat162_rn(v.z, v.w);
    uint2 o; o.x = *(uint32_t*)&a; o.y = *(uint32_t*)&b;
    ((uint2*)dst)[j] = o;
}

// ===========================================================================
// QKV projection (round-11, passing): X fp32 direct + in-register convert
// ===========================================================================
#define QKV_SMEM 49152
__global__ void __launch_bounds__(256, 3)
qkv_mma(const float* __restrict__ X,
        const __nv_bfloat16* __restrict__ Wqb, const __nv_bfloat16* __restrict__ Wkb,
        const __nv_bfloat16* __restrict__ Wvb,
        __nv_bfloat16* __restrict__ Qb, __nv_bfloat16* __restrict__ Kb,
        __nv_bfloat16* __restrict__ Vb)
{
    extern __shared__ __align__(128) char sm[];
    const uint32_t sb = smem_u32(sm);
    const int t = threadIdx.x, w = t >> 5, lane = t & 31, l7 = lane & 7;
    const int qg = w & 3, cg = w >> 2;
    const int z = blockIdx.y;
    const __nv_bfloat16* Wb = (z == 0) ? Wqb : (z == 1) ? Wkb : Wvb;
    __nv_bfloat16* Ob = (z == 0) ? Qb : (z == 1) ? Kb : Vb;
    const int rowBase = blockIdx.x * 64;
    const float* Xg = X + (size_t)rowBase * DD;
    const char* Wg = (const char*)Wb;

    float4 xr[4];
    const int xrow = t >> 4, xc4 = t & 15;
    auto ldg_x = [&](int kc){
#pragma unroll
        for (int q = 0; q < 4; q++)
            xr[q] = *(const float4*)(Xg + (size_t)(xrow + q*16)*DD + kc*64 + xc4*4);
    };
    auto sts_x = [&](int buf){
        char* xd = sm + buf*8192;
#pragma unroll
        for (int q = 0; q < 4; q++){
            int row = xrow + q*16;
            __nv_bfloat162 a = __floats2bfloat162_rn(xr[q].x, xr[q].y);
            __nv_bfloat162 b = __floats2bfloat162_rn(xr[q].z, xr[q].w);
            uint32_t off = (uint32_t)row*128u
                         + (uint32_t)((((xc4 >> 1)) ^ (row & 7)) << 4)
                         + (uint32_t)((xc4 & 1) * 8);
            uint2 v; v.x = *(uint32_t*)&a; v.y = *(uint32_t*)&b;
            *(uint2*)(xd + off) = v;
        }
    };
    auto load_w = [&](int kc, int buf){
        uint32_t wd = sb + 16384 + (uint32_t)buf * 16384;
#pragma unroll
        for (int q = 0; q < 4; q++){
            int idx = t + q*256, row = idx >> 4, ch = idx & 15;
            CP16(wd + row*256 + (uint32_t)((ch ^ (row & 7)) << 4),
                 Wg + (size_t)(kc*64 + row)*256 + ch*16);
        }
        CP_COMMIT();
    };

    float acc[8][4];
#pragma unroll
    for (int i = 0; i < 8; i++)
#pragma unroll
        for (int j = 0; j < 4; j++) acc[i][j] = 0.f;

    ldg_x(0);
    load_w(0, 0);
    load_w(1, 1);
    sts_x(0);
    ldg_x(1);

    for (int kc = 0; kc < 4; kc++){
        if (kc < 3) CP_WAIT1(); else CP_WAIT0();
        __syncthreads();
        const uint32_t xb = sb + (uint32_t)(kc & 1)*8192;
        const uint32_t wb = sb + 16384 + (uint32_t)(kc & 1)*16384;
#pragma unroll
        for (int t4 = 0; t4 < 4; t4++){
            uint32_t a[4];
            int arow = 16*qg + (lane & 15);
            int ach  = 2*t4 + (lane >> 4);
            ldsm_x4(a, xb + arow*128 + (uint32_t)((ach ^ (arow & 7)) << 4));
            int krow = 16*t4 + l7 + ((lane >> 3) & 1)*8;
#pragma unroll
            for (int u2 = 0; u2 < 4; u2++){
                uint32_t bv[4];
                int ch = 2*(4*cg + u2) + (lane >> 4);
                ldsm_x4_t(bv, wb + krow*256 + (uint32_t)((ch ^ l7) << 4));
                mma_bf16(acc[2*u2],     a, bv);
                mma_bf16(acc[2*u2 + 1], a, bv + 2);
            }
        }
        __syncthreads();
        if (kc < 3) sts_x((kc + 1) & 1);
        if (kc < 2){ ldg_x(kc + 2); load_w(kc + 2, kc & 1); }
    }

    __syncthreads();
    uint32_t* st = (uint32_t*)sm;
    {
        int r = 16*qg + (lane >> 2);
        int c2base = 32*cg + (lane & 3);
#pragma unroll
        for (int nt = 0; nt < 8; nt++){
            __nv_bfloat162 h0 = __floats2bfloat162_rn(acc[nt][0], acc[nt][1]);
            __nv_bfloat162 h1 = __floats2bfloat162_rn(acc[nt][2], acc[nt][3]);
            st[r*68 + c2base + 4*nt]       = *(uint32_t*)&h0;
            st[(r + 8)*68 + c2base + 4*nt] = *(uint32_t*)&h1;
        }
    }
    __syncthreads();
#pragma unroll
    for (int p = 0; p < 4; p++){
        int row = (t >> 4) + p*16;
        int u4  = t & 15;
        uint4 v = *(uint4*)(st + row*68 + u4*4);
        *(uint4*)(Ob + (size_t)(rowBase + row)*UU + u4*8) = v;
    }
}

// ===========================================================================
// Output projection: grid (2,128)=256 CTAs (single wave at occ 2).
// Each CTA: two 64-row subtiles sharing one W tile (loaded once).
// smem: A0 16KB @0, A1 16KB @16384, W 32KB @32768, stage 33.8KB @65536.
// ===========================================================================
#define PROJ_STAGE 65536
#define PROJ_SMEM  (PROJ_STAGE + 64*132*4)   // ~99.3KB -> occ 2
__global__ void __launch_bounds__(256, 2)
proj_mma(const __nv_bfloat16* __restrict__ Ab, const __nv_bfloat16* __restrict__ Wob,
         float* __restrict__ C, const float* __restrict__ bias,
         const float* __restrict__ res)
{
    extern __shared__ __align__(128) char sm[];
    const uint32_t sb = smem_u32(sm);
    const int t = threadIdx.x, w = t >> 5, lane = t & 31, l7 = lane & 7;
    const int qg = w & 3, cg = w >> 2;
    const int rowBase = blockIdx.y * 128, colBase = blockIdx.x * 128;

    const char* Ag = (const char*)(Ab + (size_t)rowBase * UU);
    const char* Wg = (const char*)Wob + (size_t)colBase * 2;

    // A0 (rows 0..63) + W  -> group 1
#pragma unroll
    for (int q = 0; q < 4; q++){
        int idx = t + q*256, row = idx >> 4, ch = idx & 15;
        CP16(sb + row*256 + (uint32_t)((ch ^ (row & 7)) << 4),
             Ag + (size_t)row*256 + ch*16);
    }
#pragma unroll
    for (int q = 0; q < 8; q++){
        int idx = t + q*256, row = idx >> 4, ch = idx & 15;
        CP16(sb + 32768 + row*256 + (uint32_t)((ch ^ (row & 7)) << 4),
             Wg + (size_t)row*512 + ch*16);
    }
    CP_COMMIT();
    // A1 (rows 64..127) -> group 2
#pragma unroll
    for (int q = 0; q < 4; q++){
        int idx = t + q*256, row = idx >> 4, ch = idx & 15;
        CP16(sb + 16384 + row*256 + (uint32_t)((ch ^ (row & 7)) << 4),
             Ag + (size_t)(64 + row)*256 + ch*16);
    }
    CP_COMMIT();

    CP_WAIT1();          // A0 + W ready
    __syncthreads();

    float* stg = (float*)(sm + PROJ_STAGE);

#pragma unroll
    for (int sub = 0; sub < 2; sub++){
        const uint32_t abase = sb + (uint32_t)sub * 16384;
        float acc[8][4];
#pragma unroll
        for (int i = 0; i < 8; i++)
#pragma unroll
            for (int j = 0; j < 4; j++) acc[i][j] = 0.f;

#pragma unroll
        for (int t4 = 0; t4 < 8; t4++){
            uint32_t a[4];
            int arow = 16*qg + (lane & 15);
            int ach  = 2*t4 + (lane >> 4);
            ldsm_x4(a, abase + arow*256 + (uint32_t)((ach ^ (arow & 7)) << 4));
            int krow = 16*t4 + l7 + ((lane >> 3) & 1)*8;
#pragma unroll
            for (int u2 = 0; u2 < 4; u2++){
                uint32_t bv[4];
                int ch = 2*(4*cg + u2) + (lane >> 4);
                ldsm_x4_t(bv, sb + 32768 + krow*256 + (uint32_t)((ch ^ l7) << 4));
                mma_bf16(acc[2*u2],     a, bv);
                mma_bf16(acc[2*u2 + 1], a, bv + 2);
            }
        }

        // staged coalesced epilogue (dedicated stage region)
        __syncthreads();     // prior reads of stage done (sub=1) / loads done
        {
            int r = 16*qg + (lane >> 2);
            int cb = 64*cg + 2*(lane & 3);
#pragma unroll
            for (int nt = 0; nt < 8; nt++){
                int c = cb + 8*nt;
                stg[r*132 + c]           = acc[nt][0];
                stg[r*132 + c + 1]       = acc[nt][1];
                stg[(r + 8)*132 + c]     = acc[nt][2];
                stg[(r + 8)*132 + c + 1] = acc[nt][3];
            }
        }
        __syncthreads();
        int rowB = rowBase + sub*64;
#pragma unroll
        for (int p = 0; p < 8; p++){
            int row = (t >> 5) + p*8;
            int c4  = t & 31;
            float4 v  = *(float4*)(stg + row*132 + c4*4);
            float4 bi = *(const float4*)(bias + colBase + c4*4);
            float4 rs = *(const float4*)(res + (size_t)(rowB + row)*DD + colBase + c4*4);
            v.x += bi.x + rs.x; v.y += bi.y + rs.y;
            v.z += bi.z + rs.z; v.w += bi.w + rs.w;
            *(float4*)(C + (size_t)(rowB + row)*DD + colBase + c4*4) = v;
        }
        if (sub == 0){
            CP_WAIT0();      // A1 ready
            __syncthreads();
        }
    }
}

// ===========================================================================
// Flash attention (round-11, passing): 128 q-row CTAs, m32 warp tile,
// 2-way key-split, 128-key tiles, staged O output.
// ===========================================================================
#define ATT_OSTRIDE 136
#define ATT_STAGE   73728
#define ATT_SMEM   131072

__device__ __forceinline__ void load_kv(uint32_t dst, const char* Kg, const char* Vg,
                                        int tile, int t){
    const char* ks = Kg + (size_t)tile * 128 * 256;
    const char* vs = Vg + (size_t)tile * 128 * 256;
#pragma unroll
    for (int q = 0; q < 8; q++){
        int idx = t + q*256;
        int row = idx >> 4, ch = idx & 15;
        uint32_t d = dst + row*256 + (uint32_t)((ch ^ (row & 7)) << 4);
        CP16(d,         ks + (size_t)row*256 + ch*16);
        CP16(d + 32768, vs + (size_t)row*256 + ch*16);
    }
    CP_COMMIT();
}

__global__ void __launch_bounds__(256, 1)
attn_mma(const __nv_bfloat16* __restrict__ Q, const __nv_bfloat16* __restrict__ K,
         const __nv_bfloat16* __restrict__ V, __nv_bfloat16* __restrict__ O)
{
    extern __shared__ __align__(128) char sm[];
    const uint32_t sb = smem_u32(sm);
    const int t = threadIdx.x, w = t >> 5, lane = t & 31, l7 = lane & 7;
    const int qg = w & 3, kg = w >> 2;
    const int b = blockIdx.y, qb = blockIdx.x;

    const char* Qg = (const char*)(Q + (size_t)(b*SS + qb*128)*UU);
#pragma unroll
    for (int q = 0; q < 8; q++){
        int idx = t + q*256;
        int row = idx >> 4, ch = idx & 15;
        CP16(sb + row*256 + (uint32_t)((ch ^ (row & 7)) << 4),
             Qg + (size_t)row*256 + ch*16);
    }
    CP_COMMIT();
    CP_WAIT0();
    __syncthreads();

    uint32_t qa[2][8][4];
#pragma unroll
    for (int rb = 0; rb < 2; rb++){
        int row = 32*qg + 16*rb + (lane & 15);
        int rx  = row & 7;
        int cb  = (lane >> 4) & 1;
#pragma unroll
        for (int kt = 0; kt < 8; kt++){
            int chunk = 2*kt + cb;
            ldsm_x4(qa[rb][kt], sb + row*256 + (uint32_t)((chunk ^ rx) << 4));
        }
    }
    __syncthreads();

    float oa[2][16][4];
#pragma unroll
    for (int rb = 0; rb < 2; rb++)
#pragma unroll
        for (int i = 0; i < 16; i++)
#pragma unroll
            for (int j = 0; j < 4; j++) oa[rb][i][j] = 0.f;
    float ls[2][2] = {{0.f,0.f},{0.f,0.f}};

    const char* Kg = (const char*)(K + (size_t)(b*SS)*UU);
    const char* Vg = (const char*)(V + (size_t)(b*SS)*UU);

    load_kv(sb,         Kg, Vg, 0, t);
    load_kv(sb + 65536, Kg, Vg, 1, t);

    const float C = 0.12751751699104088f;   // log2(e) / sqrt(128)

    for (int i = 0; i < 16; i++){
        if (i < 15) CP_WAIT1(); else CP_WAIT0();
        __syncthreads();
        const uint32_t kbuf = sb + (uint32_t)(i & 1)*65536;
        const uint32_t vbuf = kbuf + 32768;

#pragma unroll
        for (int tt2 = 0; tt2 < 4; tt2++){
            const int kb = 64*kg + 16*tt2;
            float sa[2][2][4];
#pragma unroll
            for (int rb = 0; rb < 2; rb++)
#pragma unroll
                for (int jj = 0; jj < 2; jj++)
#pragma unroll
                    for (int j = 0; j < 4; j++) sa[rb][jj][j] = 0.f;
#pragma unroll
            for (int jj = 0; jj < 2; jj++){
                int row = kb + 8*jj + l7;
#pragma unroll
                for (int c = 0; c < 4; c++){
                    uint32_t bv[4];
                    int chunk = 4*c + (lane >> 3);
                    ldsm_x4(bv, kbuf + row*256 + (uint32_t)((chunk ^ l7) << 4));
                    mma_bf16(sa[0][jj], qa[0][2*c],   bv);
                    mma_bf16(sa[0][jj], qa[0][2*c+1], bv + 2);
                    mma_bf16(sa[1][jj], qa[1][2*c],   bv);
                    mma_bf16(sa[1][jj], qa[1][2*c+1], bv + 2);
                }
            }
            uint32_t pa[2][4];
#pragma unroll
            for (int rb = 0; rb < 2; rb++){
                float e00 = ex2f(sa[rb][0][0]*C), e01 = ex2f(sa[rb][0][1]*C);
                float e02 = ex2f(sa[rb][0][2]*C), e03 = ex2f(sa[rb][0][3]*C);
                float e10 = ex2f(sa[rb][1][0]*C), e11 = ex2f(sa[rb][1][1]*C);
                float e12 = ex2f(sa[rb][1][2]*C), e13 = ex2f(sa[rb][1][3]*C);
                ls[rb][0] += e00 + e01 + e10 + e11;
                ls[rb][1] += e02 + e03 + e12 + e13;
                __nv_bfloat162 h;
                h = __floats2bfloat162_rn(e00, e01); pa[rb][0] = *(uint32_t*)&h;
                h = __floats2bfloat162_rn(e02, e03); pa[rb][1] = *(uint32_t*)&h;
                h = __floats2bfloat162_rn(e10, e11); pa[rb][2] = *(uint32_t*)&h;
                h = __floats2bfloat162_rn(e12, e13); pa[rb][3] = *(uint32_t*)&h;
            }
            int vrow = kb + l7 + ((lane >> 3) & 1) * 8;
#pragma unroll
            for (int u2 = 0; u2 < 8; u2++){
                uint32_t bv[4];
                int chunk = 2*u2 + (lane >> 4);
                ldsm_x4_t(bv, vbuf + vrow*256 + (uint32_t)((chunk ^ l7) << 4));
                mma_bf16(oa[0][2*u2],     pa[0], bv);
                mma_bf16(oa[0][2*u2 + 1], pa[0], bv + 2);
                mma_bf16(oa[1][2*u2],     pa[1], bv);
                mma_bf16(oa[1][2*u2 + 1], pa[1], bv + 2);
            }
        }
        if (i < 14){
            __syncthreads();
            load_kv(sb + (uint32_t)(i & 1)*65536, Kg, Vg, i + 2, t);
        }
    }

#pragma unroll
    for (int rb = 0; rb < 2; rb++)
#pragma unroll
        for (int j = 0; j < 2; j++){
            ls[rb][j] += __shfl_xor_sync(0xffffffffu, ls[rb][j], 1);
            ls[rb][j] += __shfl_xor_sync(0xffffffffu, ls[rb][j], 2);
        }

    // ---- combine key-group partials through smem ----
    float* smO = (float*)sm;
    float* smL = (float*)(sm + 128*ATT_OSTRIDE*4);
    uint32_t* stO = (uint32_t*)(sm + ATT_STAGE);
    __syncthreads();
    if (kg == 1){
#pragma unroll
        for (int rb = 0; rb < 2; rb++){
            int r0 = 32*qg + 16*rb + (lane >> 2);
            int c0 = 2*(lane & 3);
#pragma unroll
            for (int nt = 0; nt < 16; nt++){
                smO[r0*ATT_OSTRIDE + nt*8 + c0]           = oa[rb][nt][0];
                smO[r0*ATT_OSTRIDE + nt*8 + c0 + 1]       = oa[rb][nt][1];
                smO[(r0 + 8)*ATT_OSTRIDE + nt*8 + c0]     = oa[rb][nt][2];
                smO[(r0 + 8)*ATT_OSTRIDE + nt*8 + c0 + 1] = oa[rb][nt][3];
            }
            if ((lane & 3) == 0){
                smL[r0]     = ls[rb][0];
                smL[r0 + 8] = ls[rb][1];
            }
        }
    }
    __syncthreads();
    if (kg == 0){
#pragma unroll
        for (int rb = 0; rb < 2; rb++){
            int r0 = 32*qg + 16*rb + (lane >> 2);
            int c0 = 2*(lane & 3);
            float inv0 = 1.f / (ls[rb][0] + smL[r0]);
            float inv1 = 1.f / (ls[rb][1] + smL[r0 + 8]);
#pragma unroll
            for (int nt = 0; nt < 16; nt++){
                float o0 = (oa[rb][nt][0] + smO[r0*ATT_OSTRIDE + nt*8 + c0])           * inv0;
                float o1 = (oa[rb][nt][1] + smO[r0*ATT_OSTRIDE + nt*8 + c0 + 1])       * inv0;
                float o2 = (oa[rb][nt][2] + smO[(r0 + 8)*ATT_OSTRIDE + nt*8 + c0])     * inv1;
                float o3 = (oa[rb][nt][3] + smO[(r0 + 8)*ATT_OSTRIDE + nt*8 + c0 + 1]) * inv1;
                __nv_bfloat162 h0 = __floats2bfloat162_rn(o0, o1);
                __nv_bfloat162 h1 = __floats2bfloat162_rn(o2, o3);
                stO[r0*68 + 4*nt + (lane & 3)]       = *(uint32_t*)&h0;
                stO[(r0 + 8)*68 + 4*nt + (lane & 3)] = *(uint32_t*)&h1;
            }
        }
    }
    __syncthreads();
    __nv_bfloat16* Obase = O + (size_t)(b*SS + qb*128)*UU;
#pragma unroll
    for (int p = 0; p < 8; p++){
        int row = (t >> 4) + p*16;
        int u4  = t & 15;
        uint4 v = *(uint4*)(stO + row*68 + u4*4);
        *(uint4*)(Obase + (size_t)row*UU + u4*8) = v;
    }
}

// ===========================================================================
extern "C" void kernel_launch(void* const* d_in, const int* in_sizes, int n_in,
                              void* d_out, int out_size)
{
    const float* X   = (const float*)d_in[0];
    const float* W_q = (const float*)d_in[1];
    const float* W_k = (const float*)d_in[2];
    const float* W_v = (const float*)d_in[3];
    const float* W_o = (const float*)d_in[4];
    const float* b_o = (const float*)d_in[5];
    float* out = (float*)d_out;

    __nv_bfloat16 *qb, *kb, *vb, *ob, *wq, *wk, *wv, *wo;
    cudaGetSymbolAddress((void**)&qb, g_Qb);
    cudaGetSymbolAddress((void**)&kb, g_Kb);
    cudaGetSymbolAddress((void**)&vb, g_Vb);
    cudaGetSymbolAddress((void**)&ob, g_Ob);
    cudaGetSymbolAddress((void**)&wq, g_Wq);
    cudaGetSymbolAddress((void**)&wk, g_Wk);
    cudaGetSymbolAddress((void**)&wv, g_Wv);
    cudaGetSymbolAddress((void**)&wo, g_Wo);

    cudaFuncSetAttribute(qkv_mma,  cudaFuncAttributeMaxDynamicSharedMemorySize, QKV_SMEM);
    cudaFuncSetAttribute(attn_mma, cudaFuncAttributeMaxDynamicSharedMemorySize, ATT_SMEM);
    cudaFuncSetAttribute(proj_mma, cudaFuncAttributeMaxDynamicSharedMemorySize, PROJ_SMEM);

    conv_w<<<(4*NW4 + 255)/256, 256>>>(W_q, W_k, W_v, W_o, wq, wk, wv, wo);
    qkv_mma<<<dim3(MM/64, 3), 256, QKV_SMEM>>>(X, wq, wk, wv, qb, kb, vb);
    attn_mma<<<dim3(SS/128, BB), 256, ATT_SMEM>>>(qb, kb, vb, ob);
    proj_mma<<<dim3(DD/128, MM/128), 256, PROJ_SMEM>>>(ob, wo, out, b_o, X);
}

// round 14
// speedup vs baseline: 1.1551x; 1.0274x over previous
#include <cuda_runtime.h>
#include <cuda_bf16.h>
#include <cstdint>

#define BB 8
#define SS 2048
#define DD 256
#define UU 128
#define MM (BB*SS)

// ---------------- device scratch (bf16 staging) ----------------
__device__ __nv_bfloat16 g_Qb[MM*UU];
__device__ __nv_bfloat16 g_Kb[MM*UU];
__device__ __nv_bfloat16 g_Vb[MM*UU];
__device__ __nv_bfloat16 g_Wq[DD*UU], g_Wk[DD*UU], g_Wv[DD*UU];
__device__ __nv_bfloat16 g_Wo[UU*DD];

// ---------------- helpers ----------------
__device__ __forceinline__ uint32_t smem_u32(const void* p){
    uint32_t a;
    asm("{ .reg .u64 t; cvta.to.shared.u64 t, %1; cvt.u32.u64 %0, t; }":"=r"(a):"l"(p));
    return a;
}
__device__ __forceinline__ float ex2f(float x){
    float r; asm("ex2.approx.ftz.f32 %0, %1;":"=f"(r):"f"(x)); return r;
}
__device__ __forceinline__ void mma_bf16(float* c, const uint32_t* a, const uint32_t* b){
    asm volatile("mma.sync.aligned.m16n8k16.row.col.f32.bf16.bf16.f32 "
        "{%0,%1,%2,%3}, {%4,%5,%6,%7}, {%8,%9}, {%0,%1,%2,%3};"
        : "+f"(c[0]),"+f"(c[1]),"+f"(c[2]),"+f"(c[3])
        : "r"(a[0]),"r"(a[1]),"r"(a[2]),"r"(a[3]), "r"(b[0]),"r"(b[1]));
}
__device__ __forceinline__ void ldsm_x4(uint32_t* r, uint32_t addr){
    asm volatile("ldmatrix.sync.aligned.m8n8.x4.shared.b16 {%0,%1,%2,%3}, [%4];"
        : "=r"(r[0]),"=r"(r[1]),"=r"(r[2]),"=r"(r[3]) : "r"(addr));
}
__device__ __forceinline__ void ldsm_x4_t(uint32_t* r, uint32_t addr){
    asm volatile("ldmatrix.sync.aligned.m8n8.x4.trans.shared.b16 {%0,%1,%2,%3}, [%4];"
        : "=r"(r[0]),"=r"(r[1]),"=r"(r[2]),"=r"(r[3]) : "r"(addr));
}
#define CP16(dst, src) asm volatile("cp.async.cg.shared.global [%0], [%1], 16;" :: "r"(dst), "l"(src) : "memory")
#define CP_COMMIT()    asm volatile("cp.async.commit_group;" ::: "memory")
#define CP_WAIT0()     asm volatile("cp.async.wait_group 0;" ::: "memory")
#define CP_WAIT1()     asm volatile("cp.async.wait_group 1;" ::: "memory")

// ===========================================================================
// Weights fp32 -> bf16 convert
// ===========================================================================
#define NW4 (DD*UU/4)
__global__ void conv_w(const float* __restrict__ Wq, const float* __restrict__ Wk,
                       const float* __restrict__ Wv, const float* __restrict__ Wo,
                       __nv_bfloat16* __restrict__ wq, __nv_bfloat16* __restrict__ wk,
                       __nv_bfloat16* __restrict__ wv, __nv_bfloat16* __restrict__ wo)
{
    int i = blockIdx.x * blockDim.x + threadIdx.x;
    const float* src; __nv_bfloat16* dst; int j;
    if (i < NW4)              { src = Wq; dst = wq; j = i; }
    else if (i < 2*NW4)       { src = Wk; dst = wk; j = i - NW4; }
    else if (i < 3*NW4)       { src = Wv; dst = wv; j = i - 2*NW4; }
    else if (i < 4*NW4)       { src = Wo; dst = wo; j = i - 3*NW4; }
    else return;
    float4 v = ((const float4*)src)[j];
    __nv_bfloat162 a = __floats2bfloat162_rn(v.x, v.y);
    __nv_bfloat162 b = __floats2bfloat162_rn(v.z, v.w);
    uint2 o; o.x = *(uint32_t*)&a; o.y = *(uint32_t*)&b;
    ((uint2*)dst)[j] = o;
}

// ===========================================================================
// QKV projection (round-11, passing): X fp32 direct + in-register convert
// ===========================================================================
#define QKV_SMEM 49152
__global__ void __launch_bounds__(256, 3)
qkv_mma(const float* __restrict__ X,
        const __nv_bfloat16* __restrict__ Wqb, const __nv_bfloat16* __restrict__ Wkb,
        const __nv_bfloat16* __restrict__ Wvb,
        __nv_bfloat16* __restrict__ Qb, __nv_bfloat16* __restrict__ Kb,
        __nv_bfloat16* __restrict__ Vb)
{
    extern __shared__ __align__(128) char sm[];
    const uint32_t sb = smem_u32(sm);
    const int t = threadIdx.x, w = t >> 5, lane = t & 31, l7 = lane & 7;
    const int qg = w & 3, cg = w >> 2;
    const int z = blockIdx.y;
    const __nv_bfloat16* Wb = (z == 0) ? Wqb : (z == 1) ? Wkb : Wvb;
    __nv_bfloat16* Ob = (z == 0) ? Qb : (z == 1) ? Kb : Vb;
    const int rowBase = blockIdx.x * 64;
    const float* Xg = X + (size_t)rowBase * DD;
    const char* Wg = (const char*)Wb;

    float4 xr[4];
    const int xrow = t >> 4, xc4 = t & 15;
    auto ldg_x = [&](int kc){
#pragma unroll
        for (int q = 0; q < 4; q++)
            xr[q] = *(const float4*)(Xg + (size_t)(xrow + q*16)*DD + kc*64 + xc4*4);
    };
    auto sts_x = [&](int buf){
        char* xd = sm + buf*8192;
#pragma unroll
        for (int q = 0; q < 4; q++){
            int row = xrow + q*16;
            __nv_bfloat162 a = __floats2bfloat162_rn(xr[q].x, xr[q].y);
            __nv_bfloat162 b = __floats2bfloat162_rn(xr[q].z, xr[q].w);
            uint32_t off = (uint32_t)row*128u
                         + (uint32_t)((((xc4 >> 1)) ^ (row & 7)) << 4)
                         + (uint32_t)((xc4 & 1) * 8);
            uint2 v; v.x = *(uint32_t*)&a; v.y = *(uint32_t*)&b;
            *(uint2*)(xd + off) = v;
        }
    };
    auto load_w = [&](int kc, int buf){
        uint32_t wd = sb + 16384 + (uint32_t)buf * 16384;
#pragma unroll
        for (int q = 0; q < 4; q++){
            int idx = t + q*256, row = idx >> 4, ch = idx & 15;
            CP16(wd + row*256 + (uint32_t)((ch ^ (row & 7)) << 4),
                 Wg + (size_t)(kc*64 + row)*256 + ch*16);
        }
        CP_COMMIT();
    };

    float acc[8][4];
#pragma unroll
    for (int i = 0; i < 8; i++)
#pragma unroll
        for (int j = 0; j < 4; j++) acc[i][j] = 0.f;

    ldg_x(0);
    load_w(0, 0);
    load_w(1, 1);
    sts_x(0);
    ldg_x(1);

    for (int kc = 0; kc < 4; kc++){
        if (kc < 3) CP_WAIT1(); else CP_WAIT0();
        __syncthreads();
        const uint32_t xb = sb + (uint32_t)(kc & 1)*8192;
        const uint32_t wb = sb + 16384 + (uint32_t)(kc & 1)*16384;
#pragma unroll
        for (int t4 = 0; t4 < 4; t4++){
            uint32_t a[4];
            int arow = 16*qg + (lane & 15);
            int ach  = 2*t4 + (lane >> 4);
            ldsm_x4(a, xb + arow*128 + (uint32_t)((ach ^ (arow & 7)) << 4));
            int krow = 16*t4 + l7 + ((lane >> 3) & 1)*8;
#pragma unroll
            for (int u2 = 0; u2 < 4; u2++){
                uint32_t bv[4];
                int ch = 2*(4*cg + u2) + (lane >> 4);
                ldsm_x4_t(bv, wb + krow*256 + (uint32_t)((ch ^ l7) << 4));
                mma_bf16(acc[2*u2],     a, bv);
                mma_bf16(acc[2*u2 + 1], a, bv + 2);
            }
        }
        __syncthreads();
        if (kc < 3) sts_x((kc + 1) & 1);
        if (kc < 2){ ldg_x(kc + 2); load_w(kc + 2, kc & 1); }
    }

    __syncthreads();
    uint32_t* st = (uint32_t*)sm;
    {
        int r = 16*qg + (lane >> 2);
        int c2base = 32*cg + (lane & 3);
#pragma unroll
        for (int nt = 0; nt < 8; nt++){
            __nv_bfloat162 h0 = __floats2bfloat162_rn(acc[nt][0], acc[nt][1]);
            __nv_bfloat162 h1 = __floats2bfloat162_rn(acc[nt][2], acc[nt][3]);
            st[r*68 + c2base + 4*nt]       = *(uint32_t*)&h0;
            st[(r + 8)*68 + c2base + 4*nt] = *(uint32_t*)&h1;
        }
    }
    __syncthreads();
#pragma unroll
    for (int p = 0; p < 4; p++){
        int row = (t >> 4) + p*16;
        int u4  = t & 15;
        uint4 v = *(uint4*)(st + row*68 + u4*4);
        *(uint4*)(Ob + (size_t)(rowBase + row)*UU + u4*8) = v;
    }
}

// ===========================================================================
// Flash attention + FUSED output projection.
// Mainloop: round-11 structure (128 q-rows, m32 warp tile, 2-way key split,
// 128-key tiles). Epilogue: combined O written to swizzled smem tile, then
// 128x256x128 bf16 mma against prefetched Wo, +bias +residual, fp32 out.
// smem: [0,128K) KV double buffer / combine / stage; [128K,192K) Wo tile.
// ===========================================================================
#define ATT_OSTRIDE 136
#define ATT_OTILE   73728                  // swizzled O tile (32KB), inside buf1
#define ATT_WO      131072                 // Wo tile 64KB
#define ATT_SMEM    (ATT_WO + 65536)       // 192KB

__device__ __forceinline__ void load_kv(uint32_t dst, const char* Kg, const char* Vg,
                                        int tile, int t){
    const char* ks = Kg + (size_t)tile * 128 * 256;
    const char* vs = Vg + (size_t)tile * 128 * 256;
#pragma unroll
    for (int q = 0; q < 8; q++){
        int idx = t + q*256;
        int row = idx >> 4, ch = idx & 15;
        uint32_t d = dst + row*256 + (uint32_t)((ch ^ (row & 7)) << 4);
        CP16(d,         ks + (size_t)row*256 + ch*16);
        CP16(d + 32768, vs + (size_t)row*256 + ch*16);
    }
    CP_COMMIT();
}

__global__ void __launch_bounds__(256, 1)
attn_mma(const __nv_bfloat16* __restrict__ Q, const __nv_bfloat16* __restrict__ K,
         const __nv_bfloat16* __restrict__ V, const __nv_bfloat16* __restrict__ Wob,
         const float* __restrict__ bias, const float* __restrict__ res,
         float* __restrict__ out)
{
    extern __shared__ __align__(128) char sm[];
    const uint32_t sb = smem_u32(sm);
    const int t = threadIdx.x, w = t >> 5, lane = t & 31, l7 = lane & 7;
    const int qg = w & 3, kg = w >> 2;
    const int b = blockIdx.y, qb = blockIdx.x;

    // ---- prefetch Wo (64KB, 512B rows, swizzled) + stage Q ----
    const char* Wg = (const char*)Wob;
#pragma unroll
    for (int q = 0; q < 16; q++){
        int idx = t + q*256;               // 0..4095
        int row = idx >> 5, ch = idx & 31;
        CP16(sb + ATT_WO + row*512 + (uint32_t)((ch ^ (row & 7)) << 4),
             Wg + (size_t)row*512 + ch*16);
    }
    const char* Qg = (const char*)(Q + (size_t)(b*SS + qb*128)*UU);
#pragma unroll
    for (int q = 0; q < 8; q++){
        int idx = t + q*256;
        int row = idx >> 4, ch = idx & 15;
        CP16(sb + row*256 + (uint32_t)((ch ^ (row & 7)) << 4),
             Qg + (size_t)row*256 + ch*16);
    }
    CP_COMMIT();
    CP_WAIT0();
    __syncthreads();

    uint32_t qa[2][8][4];
#pragma unroll
    for (int rb = 0; rb < 2; rb++){
        int row = 32*qg + 16*rb + (lane & 15);
        int rx  = row & 7;
        int cb  = (lane >> 4) & 1;
#pragma unroll
        for (int kt = 0; kt < 8; kt++){
            int chunk = 2*kt + cb;
            ldsm_x4(qa[rb][kt], sb + row*256 + (uint32_t)((chunk ^ rx) << 4));
        }
    }
    __syncthreads();

    float oa[2][16][4];
#pragma unroll
    for (int rb = 0; rb < 2; rb++)
#pragma unroll
        for (int i = 0; i < 16; i++)
#pragma unroll
            for (int j = 0; j < 4; j++) oa[rb][i][j] = 0.f;
    float ls[2][2] = {{0.f,0.f},{0.f,0.f}};

    const char* Kg = (const char*)(K + (size_t)(b*SS)*UU);
    const char* Vg = (const char*)(V + (size_t)(b*SS)*UU);

    load_kv(sb,         Kg, Vg, 0, t);
    load_kv(sb + 65536, Kg, Vg, 1, t);

    const float C = 0.12751751699104088f;   // log2(e) / sqrt(128)

    for (int i = 0; i < 16; i++){
        if (i < 15) CP_WAIT1(); else CP_WAIT0();
        __syncthreads();
        const uint32_t kbuf = sb + (uint32_t)(i & 1)*65536;
        const uint32_t vbuf = kbuf + 32768;

#pragma unroll
        for (int tt2 = 0; tt2 < 4; tt2++){
            const int kb = 64*kg + 16*tt2;
            float sa[2][2][4];
#pragma unroll
            for (int rb = 0; rb < 2; rb++)
#pragma unroll
                for (int jj = 0; jj < 2; jj++)
#pragma unroll
                    for (int j = 0; j < 4; j++) sa[rb][jj][j] = 0.f;
#pragma unroll
            for (int jj = 0; jj < 2; jj++){
                int row = kb + 8*jj + l7;
#pragma unroll
                for (int c = 0; c < 4; c++){
                    uint32_t bv[4];
                    int chunk = 4*c + (lane >> 3);
                    ldsm_x4(bv, kbuf + row*256 + (uint32_t)((chunk ^ l7) << 4));
                    mma_bf16(sa[0][jj], qa[0][2*c],   bv);
                    mma_bf16(sa[0][jj], qa[0][2*c+1], bv + 2);
                    mma_bf16(sa[1][jj], qa[1][2*c],   bv);
                    mma_bf16(sa[1][jj], qa[1][2*c+1], bv + 2);
                }
            }
            uint32_t pa[2][4];
#pragma unroll
            for (int rb = 0; rb < 2; rb++){
                float e00 = ex2f(sa[rb][0][0]*C), e01 = ex2f(sa[rb][0][1]*C);
                float e02 = ex2f(sa[rb][0][2]*C), e03 = ex2f(sa[rb][0][3]*C);
                float e10 = ex2f(sa[rb][1][0]*C), e11 = ex2f(sa[rb][1][1]*C);
                float e12 = ex2f(sa[rb][1][2]*C), e13 = ex2f(sa[rb][1][3]*C);
                ls[rb][0] += e00 + e01 + e10 + e11;
                ls[rb][1] += e02 + e03 + e12 + e13;
                __nv_bfloat162 h;
                h = __floats2bfloat162_rn(e00, e01); pa[rb][0] = *(uint32_t*)&h;
                h = __floats2bfloat162_rn(e02, e03); pa[rb][1] = *(uint32_t*)&h;
                h = __floats2bfloat162_rn(e10, e11); pa[rb][2] = *(uint32_t*)&h;
                h = __floats2bfloat162_rn(e12, e13); pa[rb][3] = *(uint32_t*)&h;
            }
            int vrow = kb + l7 + ((lane >> 3) & 1) * 8;
#pragma unroll
            for (int u2 = 0; u2 < 8; u2++){
                uint32_t bv[4];
                int chunk = 2*u2 + (lane >> 4);
                ldsm_x4_t(bv, vbuf + vrow*256 + (uint32_t)((chunk ^ l7) << 4));
                mma_bf16(oa[0][2*u2],     pa[0], bv);
                mma_bf16(oa[0][2*u2 + 1], pa[0], bv + 2);
                mma_bf16(oa[1][2*u2],     pa[1], bv);
                mma_bf16(oa[1][2*u2 + 1], pa[1], bv + 2);
            }
        }
        if (i < 14){
            __syncthreads();
            load_kv(sb + (uint32_t)(i & 1)*65536, Kg, Vg, i + 2, t);
        }
    }

#pragma unroll
    for (int rb = 0; rb < 2; rb++)
#pragma unroll
        for (int j = 0; j < 2; j++){
            ls[rb][j] += __shfl_xor_sync(0xffffffffu, ls[rb][j], 1);
            ls[rb][j] += __shfl_xor_sync(0xffffffffu, ls[rb][j], 2);
        }

    // ---- key-group combine; write O into swizzled ldsm-ready tile ----
    float* smO = (float*)sm;
    float* smL = (float*)(sm + 128*ATT_OSTRIDE*4);
    __syncthreads();
    if (kg == 1){
#pragma unroll
        for (int rb = 0; rb < 2; rb++){
            int r0 = 32*qg + 16*rb + (lane >> 2);
            int c0 = 2*(lane & 3);
#pragma unroll
            for (int nt = 0; nt < 16; nt++){
                smO[r0*ATT_OSTRIDE + nt*8 + c0]           = oa[rb][nt][0];
                smO[r0*ATT_OSTRIDE + nt*8 + c0 + 1]       = oa[rb][nt][1];
                smO[(r0 + 8)*ATT_OSTRIDE + nt*8 + c0]     = oa[rb][nt][2];
                smO[(r0 + 8)*ATT_OSTRIDE + nt*8 + c0 + 1] = oa[rb][nt][3];
            }
            if ((lane & 3) == 0){
                smL[r0]     = ls[rb][0];
                smL[r0 + 8] = ls[rb][1];
            }
        }
    }
    __syncthreads();
    if (kg == 0){
#pragma unroll
        for (int rb = 0; rb < 2; rb++){
            int r0 = 32*qg + 16*rb + (lane >> 2);
            int c0 = 2*(lane & 3);
            float inv0 = 1.f / (ls[rb][0] + smL[r0]);
            float inv1 = 1.f / (ls[rb][1] + smL[r0 + 8]);
#pragma unroll
            for (int nt = 0; nt < 16; nt++){
                float o0 = (oa[rb][nt][0] + smO[r0*ATT_OSTRIDE + nt*8 + c0])           * inv0;
                float o1 = (oa[rb][nt][1] + smO[r0*ATT_OSTRIDE + nt*8 + c0 + 1])       * inv0;
                float o2 = (oa[rb][nt][2] + smO[(r0 + 8)*ATT_OSTRIDE + nt*8 + c0])     * inv1;
                float o3 = (oa[rb][nt][3] + smO[(r0 + 8)*ATT_OSTRIDE + nt*8 + c0 + 1]) * inv1;
                __nv_bfloat162 h0 = __floats2bfloat162_rn(o0, o1);
                __nv_bfloat162 h1 = __floats2bfloat162_rn(o2, o3);
                // swizzled O-tile store (256B rows): row*256 + ((nt^(row&7))<<4) + 4*(lane&3)
                *(uint32_t*)(sm + ATT_OTILE + r0*256
                    + (uint32_t)(((nt ^ (r0 & 7)) << 4)) + 4*(lane & 3))       = *(uint32_t*)&h0;
                *(uint32_t*)(sm + ATT_OTILE + (r0 + 8)*256
                    + (uint32_t)(((nt ^ ((r0 + 8) & 7)) << 4)) + 4*(lane & 3)) = *(uint32_t*)&h1;
            }
        }
    }
    __syncthreads();

    // ---- fused projection: [128x128 O] x [128x256 Wo] ----
    const uint32_t OT = sb + ATT_OTILE;
    const uint32_t WT = sb + ATT_WO;
    float po[2][16][4];
#pragma unroll
    for (int rb = 0; rb < 2; rb++)
#pragma unroll
        for (int i = 0; i < 16; i++)
#pragma unroll
            for (int j = 0; j < 4; j++) po[rb][i][j] = 0.f;
    const int pqg = w & 3, pcg = w >> 2;

#pragma unroll
    for (int t4 = 0; t4 < 8; t4++){
        uint32_t a0[4], a1[4];
        int ach = 2*t4 + (lane >> 4);
        int ar0 = 32*pqg + (lane & 15);
        int ar1 = ar0 + 16;
        ldsm_x4(a0, OT + ar0*256 + (uint32_t)((ach ^ (ar0 & 7)) << 4));
        ldsm_x4(a1, OT + ar1*256 + (uint32_t)((ach ^ (ar1 & 7)) << 4));
        int krow = 16*t4 + l7 + ((lane >> 3) & 1)*8;
#pragma unroll
        for (int u2 = 0; u2 < 8; u2++){
            uint32_t bv[4];
            int ch = 16*pcg + 2*u2 + (lane >> 4);
            ldsm_x4_t(bv, WT + krow*512 + (uint32_t)((ch ^ l7) << 4));
            mma_bf16(po[0][2*u2],     a0, bv);
            mma_bf16(po[0][2*u2 + 1], a0, bv + 2);
            mma_bf16(po[1][2*u2],     a1, bv);
            mma_bf16(po[1][2*u2 + 1], a1, bv + 2);
        }
    }
    __syncthreads();   // everyone done reading OT/WT; smem reusable for stage

    // ---- stage fp32 [128][260] then coalesced +bias +res write ----
    float* stg = (float*)sm;
#pragma unroll
    for (int rb = 0; rb < 2; rb++){
        int r = 32*pqg + 16*rb + (lane >> 2);
#pragma unroll
        for (int nt = 0; nt < 16; nt++){
            int c = 128*pcg + 8*nt + 2*(lane & 3);
            stg[r*260 + c]           = po[rb][nt][0];
            stg[r*260 + c + 1]       = po[rb][nt][1];
            stg[(r + 8)*260 + c]     = po[rb][nt][2];
            stg[(r + 8)*260 + c + 1] = po[rb][nt][3];
        }
    }
    __syncthreads();

    const int rowG = b*SS + qb*128;
    const int c4 = t & 63;
    const int rb0 = t >> 6;
    float4 bi = *(const float4*)(bias + c4*4);
#pragma unroll
    for (int p = 0; p < 32; p++){
        int row = rb0 + 4*p;
        float4 v  = *(float4*)(stg + row*260 + c4*4);
        float4 rs = *(const float4*)(res + (size_t)(rowG + row)*DD + c4*4);
        v.x += bi.x + rs.x; v.y += bi.y + rs.y;
        v.z += bi.z + rs.z; v.w += bi.w + rs.w;
        *(float4*)(out + (size_t)(rowG + row)*DD + c4*4) = v;
    }
}

// ===========================================================================
extern "C" void kernel_launch(void* const* d_in, const int* in_sizes, int n_in,
                              void* d_out, int out_size)
{
    const float* X   = (const float*)d_in[0];
    const float* W_q = (const float*)d_in[1];
    const float* W_k = (const float*)d_in[2];
    const float* W_v = (const float*)d_in[3];
    const float* W_o = (const float*)d_in[4];
    const float* b_o = (const float*)d_in[5];
    float* out = (float*)d_out;

    __nv_bfloat16 *qb, *kb, *vb, *wq, *wk, *wv, *wo;
    cudaGetSymbolAddress((void**)&qb, g_Qb);
    cudaGetSymbolAddress((void**)&kb, g_Kb);
    cudaGetSymbolAddress((void**)&vb, g_Vb);
    cudaGetSymbolAddress((void**)&wq, g_Wq);
    cudaGetSymbolAddress((void**)&wk, g_Wk);
    cudaGetSymbolAddress((void**)&wv, g_Wv);
    cudaGetSymbolAddress((void**)&wo, g_Wo);

    cudaFuncSetAttribute(qkv_mma,  cudaFuncAttributeMaxDynamicSharedMemorySize, QKV_SMEM);
    cudaFuncSetAttribute(attn_mma, cudaFuncAttributeMaxDynamicSharedMemorySize, ATT_SMEM);

    conv_w<<<(4*NW4 + 255)/256, 256>>>(W_q, W_k, W_v, W_o, wq, wk, wv, wo);
    qkv_mma<<<dim3(MM/64, 3), 256, QKV_SMEM>>>(X, wq, wk, wv, qb, kb, vb);
    attn_mma<<<dim3(SS/128, BB), 256, ATT_SMEM>>>(qb, kb, vb, wo, b_o, X, out);
}